// round 15
// baseline (speedup 1.0000x reference)
#include <cuda_runtime.h>
#include <cstdint>

#define TPB 256

__device__ __forceinline__ float4 ldg_el(const float4* p, uint64_t pol) {
    float4 v;
    asm volatile("ld.global.nc.L2::cache_hint.v4.f32 {%0,%1,%2,%3}, [%4], %5;"
                 : "=f"(v.x), "=f"(v.y), "=f"(v.z), "=f"(v.w)
                 : "l"(p), "l"(pol));
    return v;
}
__device__ __forceinline__ float2 ldg_el2(const float2* p, uint64_t pol) {
    float2 v;
    asm volatile("ld.global.nc.L2::cache_hint.v2.f32 {%0,%1}, [%2], %3;"
                 : "=f"(v.x), "=f"(v.y)
                 : "l"(p), "l"(pol));
    return v;
}
__device__ __forceinline__ void stg_cs2(float2* p, float2 v) {
    asm volatile("st.global.cs.v2.f32 [%0], {%1,%2};"
                 :: "l"(p), "f"(v.x), "f"(v.y) : "memory");
}

__global__ void __launch_bounds__(TPB) encoder_persist_l2_kernel(
    const float* __restrict__ x,   // [N,10]
    const float* __restrict__ t,   // [N,1]
    const float* __restrict__ y,   // [N,1]
    const float* __restrict__ w,   // [2048]
    const float* __restrict__ b,   // [2048]
    float* __restrict__ out,       // [N,1]
    int n)
{
    __shared__ float2 swb[2048];   // interleaved (w,b): 16 KB

    const int tid = threadIdx.x;

    // evict_last policy for the read streams (L2-resident across replays)
    uint64_t pol;
    asm volatile("createpolicy.fractional.L2::evict_last.b64 %0, 1.0;" : "=l"(pol));

    // ---- build (w,b) table once per CTA ----
#pragma unroll
    for (int j = 0; j < 2; ++j) {
        int k = tid + j * TPB;                   // float4 index 0..511
        float4 wv = __ldg((const float4*)w + k);
        float4 bv = __ldg((const float4*)b + k);
        swb[4 * k + 0] = make_float2(wv.x, bv.x);
        swb[4 * k + 1] = make_float2(wv.y, bv.y);
        swb[4 * k + 2] = make_float2(wv.z, bv.z);
        swb[4 * k + 3] = make_float2(wv.w, bv.w);
    }
    __syncthreads();

    const int nth   = gridDim.x * TPB;
    const int nfull = n >> 1;                    // full row-pairs

    // odd final row (generic-n safety)
    if ((n & 1) && blockIdx.x == 0 && tid == 0) {
        const float* xr = x + (size_t)(n - 1) * 10;
        int idx = 0;
#pragma unroll
        for (int j = 0; j < 10; ++j)
            idx = (idx << 1) | (xr[j] != 0.f ? 1 : 0);
        idx |= (t[n - 1] != 0.f ? 1 : 0) << 10;
        float2 wb = swb[idx];
        out[n - 1] = fmaf(y[n - 1], wb.x, wb.y);
    }

    // ---- persistent grid-stride loop (no barriers, L2-pinned reads) ----
    for (int p = blockIdx.x * TPB + tid; p < nfull; p += nth) {
        const int i0 = p * 2;
        const float4* xv = (const float4*)(x + (size_t)i0 * 10);

        float4 f0 = ldg_el(xv + 0, pol);
        float4 f1 = ldg_el(xv + 1, pol);
        float4 f2 = ldg_el(xv + 2, pol);
        float4 f3 = ldg_el(xv + 3, pol);
        float4 f4 = ldg_el(xv + 4, pol);
        float2 tv = ldg_el2((const float2*)(t + i0), pol);
        float2 yv = ldg_el2((const float2*)(y + i0), pol);

        const int idx0 =
            ((f0.x != 0.f) << 9) | ((f0.y != 0.f) << 8) |
            ((f0.z != 0.f) << 7) | ((f0.w != 0.f) << 6) |
            ((f1.x != 0.f) << 5) | ((f1.y != 0.f) << 4) |
            ((f1.z != 0.f) << 3) | ((f1.w != 0.f) << 2) |
            ((f2.x != 0.f) << 1) | ((f2.y != 0.f) << 0) |
            ((tv.x != 0.f) << 10);
        const int idx1 =
            ((f2.z != 0.f) << 9) | ((f2.w != 0.f) << 8) |
            ((f3.x != 0.f) << 7) | ((f3.y != 0.f) << 6) |
            ((f3.z != 0.f) << 5) | ((f3.w != 0.f) << 4) |
            ((f4.x != 0.f) << 3) | ((f4.y != 0.f) << 2) |
            ((f4.z != 0.f) << 1) | ((f4.w != 0.f) << 0) |
            ((tv.y != 0.f) << 10);

        float2 wb0 = swb[idx0];
        float2 wb1 = swb[idx1];
        float2 o;
        o.x = fmaf(yv.x, wb0.x, wb0.y);
        o.y = fmaf(yv.y, wb1.x, wb1.y);
        stg_cs2((float2*)(out + i0), o);
    }
}

extern "C" void kernel_launch(void* const* d_in, const int* in_sizes, int n_in,
                              void* d_out, int out_size)
{
    const float* x = (const float*)d_in[0];
    const float* t = (const float*)d_in[1];
    const float* y = (const float*)d_in[2];
    const float* w = (const float*)d_in[3];
    const float* b = (const float*)d_in[4];
    float* out = (float*)d_out;

    int n = in_sizes[1];
    int nfull = n >> 1;
    int blocks = 8 * 152;                         // one full resident wave on GB300
    int needed = (nfull + TPB - 1) / TPB;
    if (blocks > needed) blocks = needed;
    if (blocks < 1) blocks = 1;
    encoder_persist_l2_kernel<<<blocks, TPB>>>(x, t, y, w, b, out, n);
}

// round 16
// speedup vs baseline: 1.7432x; 1.7432x over previous
#include <cuda_runtime.h>
#include <cstdint>

#define TPB 256

__global__ void __launch_bounds__(TPB) encoder_persist_tab2_kernel(
    const float* __restrict__ x,   // [N,10]
    const float* __restrict__ t,   // [N,1]
    const float* __restrict__ y,   // [N,1]
    const float* __restrict__ w,   // [2048]
    const float* __restrict__ b,   // [2048]
    float* __restrict__ out,       // [N,1]
    int n)
{
    __shared__ float2 swb[2048];   // interleaved (w,b): 16 KB

    const int tid = threadIdx.x;

    // ---- build (w,b) table once per CTA ----
#pragma unroll
    for (int j = 0; j < 2; ++j) {
        int k = tid + j * TPB;                   // float4 index 0..511
        float4 wv = __ldg((const float4*)w + k);
        float4 bv = __ldg((const float4*)b + k);
        swb[4 * k + 0] = make_float2(wv.x, bv.x);
        swb[4 * k + 1] = make_float2(wv.y, bv.y);
        swb[4 * k + 2] = make_float2(wv.z, bv.z);
        swb[4 * k + 3] = make_float2(wv.w, bv.w);
    }
    __syncthreads();

    const int nth   = gridDim.x * TPB;
    const int nfull = n >> 1;                    // full row-pairs

    // odd final row (generic-n safety)
    if ((n & 1) && blockIdx.x == 0 && tid == 0) {
        const float* xr = x + (size_t)(n - 1) * 10;
        int idx = 0;
#pragma unroll
        for (int j = 0; j < 10; ++j)
            idx = (idx << 1) | (xr[j] != 0.f ? 1 : 0);
        idx |= (t[n - 1] != 0.f ? 1 : 0) << 10;
        float2 wb = swb[idx];
        out[n - 1] = fmaf(y[n - 1], wb.x, wb.y);
    }

    // ---- persistent grid-stride loop over row pairs (no barriers) ----
    for (int p = blockIdx.x * TPB + tid; p < nfull; p += nth) {
        const int i0 = p * 2;
        const float4* xv = (const float4*)(x + (size_t)i0 * 10);

        // small streams first in the front batch, then 5 independent LDG.128
        float2 tv = __ldg((const float2*)(t + i0));
        float2 yv = __ldg((const float2*)(y + i0));
        float4 f0 = __ldg(xv + 0);
        float4 f1 = __ldg(xv + 1);
        float4 f2 = __ldg(xv + 2);
        float4 f3 = __ldg(xv + 3);
        float4 f4 = __ldg(xv + 4);

        const int idx0 =
            ((f0.x != 0.f) << 9) | ((f0.y != 0.f) << 8) |
            ((f0.z != 0.f) << 7) | ((f0.w != 0.f) << 6) |
            ((f1.x != 0.f) << 5) | ((f1.y != 0.f) << 4) |
            ((f1.z != 0.f) << 3) | ((f1.w != 0.f) << 2) |
            ((f2.x != 0.f) << 1) | ((f2.y != 0.f) << 0) |
            ((tv.x != 0.f) << 10);
        const int idx1 =
            ((f2.z != 0.f) << 9) | ((f2.w != 0.f) << 8) |
            ((f3.x != 0.f) << 7) | ((f3.y != 0.f) << 6) |
            ((f3.z != 0.f) << 5) | ((f3.w != 0.f) << 4) |
            ((f4.x != 0.f) << 3) | ((f4.y != 0.f) << 2) |
            ((f4.z != 0.f) << 1) | ((f4.w != 0.f) << 0) |
            ((tv.y != 0.f) << 10);

        float2 wb0 = swb[idx0];
        float2 wb1 = swb[idx1];
        float2 o;
        o.x = fmaf(yv.x, wb0.x, wb0.y);
        o.y = fmaf(yv.y, wb1.x, wb1.y);
        __stcs((float2*)(out + i0), o);   // streaming store: don't pollute L2
    }
}

extern "C" void kernel_launch(void* const* d_in, const int* in_sizes, int n_in,
                              void* d_out, int out_size)
{
    const float* x = (const float*)d_in[0];
    const float* t = (const float*)d_in[1];
    const float* y = (const float*)d_in[2];
    const float* w = (const float*)d_in[3];
    const float* b = (const float*)d_in[4];
    float* out = (float*)d_out;

    int n = in_sizes[1];
    int nfull = n >> 1;
    int blocks = 8 * 152;                         // one full resident wave on GB300
    int needed = (nfull + TPB - 1) / TPB;
    if (blocks > needed) blocks = needed;
    if (blocks < 1) blocks = 1;
    encoder_persist_tab2_kernel<<<blocks, TPB>>>(x, t, y, w, b, out, n);
}

// round 17
// speedup vs baseline: 1.7505x; 1.0042x over previous
#include <cuda_runtime.h>
#include <cstdint>

#define TPB 512

__global__ void __launch_bounds__(TPB) encoder_persist_tab3_kernel(
    const float* __restrict__ x,   // [N,10]
    const float* __restrict__ t,   // [N,1]
    const float* __restrict__ y,   // [N,1]
    const float* __restrict__ w,   // [2048]
    const float* __restrict__ b,   // [2048]
    float* __restrict__ out,       // [N,1]
    int n)
{
    __shared__ float2 swb[2048];   // interleaved (w,b): 16 KB

    const int tid = threadIdx.x;

    // ---- build (w,b) table: exactly one float4 of each per thread ----
    {
        float4 wv = __ldg((const float4*)w + tid);   // tid in [0,512)
        float4 bv = __ldg((const float4*)b + tid);
        swb[4 * tid + 0] = make_float2(wv.x, bv.x);
        swb[4 * tid + 1] = make_float2(wv.y, bv.y);
        swb[4 * tid + 2] = make_float2(wv.z, bv.z);
        swb[4 * tid + 3] = make_float2(wv.w, bv.w);
    }
    __syncthreads();

    const int nth   = gridDim.x * TPB;
    const int nfull = n >> 1;                    // full row-pairs

    // odd final row (generic-n safety)
    if ((n & 1) && blockIdx.x == 0 && tid == 0) {
        const float* xr = x + (size_t)(n - 1) * 10;
        int idx = 0;
#pragma unroll
        for (int j = 0; j < 10; ++j)
            idx = (idx << 1) | (xr[j] != 0.f ? 1 : 0);
        idx |= (t[n - 1] != 0.f ? 1 : 0) << 10;
        float2 wb = swb[idx];
        out[n - 1] = fmaf(y[n - 1], wb.x, wb.y);
    }

    // ---- persistent grid-stride loop over row pairs (no barriers) ----
    for (int p = blockIdx.x * TPB + tid; p < nfull; p += nth) {
        const int i0 = p * 2;
        const float4* xv = (const float4*)(x + (size_t)i0 * 10);

        // small streams first in the front batch, then 5 independent LDG.128
        float2 tv = __ldg((const float2*)(t + i0));
        float2 yv = __ldg((const float2*)(y + i0));
        float4 f0 = __ldg(xv + 0);
        float4 f1 = __ldg(xv + 1);
        float4 f2 = __ldg(xv + 2);
        float4 f3 = __ldg(xv + 3);
        float4 f4 = __ldg(xv + 4);

        const int idx0 =
            ((f0.x != 0.f) << 9) | ((f0.y != 0.f) << 8) |
            ((f0.z != 0.f) << 7) | ((f0.w != 0.f) << 6) |
            ((f1.x != 0.f) << 5) | ((f1.y != 0.f) << 4) |
            ((f1.z != 0.f) << 3) | ((f1.w != 0.f) << 2) |
            ((f2.x != 0.f) << 1) | ((f2.y != 0.f) << 0) |
            ((tv.x != 0.f) << 10);
        const int idx1 =
            ((f2.z != 0.f) << 9) | ((f2.w != 0.f) << 8) |
            ((f3.x != 0.f) << 7) | ((f3.y != 0.f) << 6) |
            ((f3.z != 0.f) << 5) | ((f3.w != 0.f) << 4) |
            ((f4.x != 0.f) << 3) | ((f4.y != 0.f) << 2) |
            ((f4.z != 0.f) << 1) | ((f4.w != 0.f) << 0) |
            ((tv.y != 0.f) << 10);

        float2 wb0 = swb[idx0];
        float2 wb1 = swb[idx1];
        float2 o;
        o.x = fmaf(yv.x, wb0.x, wb0.y);
        o.y = fmaf(yv.y, wb1.x, wb1.y);
        __stcs((float2*)(out + i0), o);   // streaming store: don't pollute L2
    }
}

extern "C" void kernel_launch(void* const* d_in, const int* in_sizes, int n_in,
                              void* d_out, int out_size)
{
    const float* x = (const float*)d_in[0];
    const float* t = (const float*)d_in[1];
    const float* y = (const float*)d_in[2];
    const float* w = (const float*)d_in[3];
    const float* b = (const float*)d_in[4];
    float* out = (float*)d_out;

    int n = in_sizes[1];
    int nfull = n >> 1;
    int blocks = 4 * 152;                         // one full resident wave on GB300
    int needed = (nfull + TPB - 1) / TPB;
    if (blocks > needed) blocks = needed;
    if (blocks < 1) blocks = 1;
    encoder_persist_tab3_kernel<<<blocks, TPB>>>(x, t, y, w, b, out, n);
}